// round 13
// baseline (speedup 1.0000x reference)
#include <cuda_runtime.h>
#include <cstdint>

#define NN 50000
#define EE 800000
#define FIN 500
#define HH 64
#define CO 16
#define SCAN_B 49     // ceil(NN/1024)
#define BSTRIDE 136   // B smem row stride in floats
#define K0PAD 504     // FIN padded to multiple of 8

// ---------------- scratch (device globals; allocation-free) ----------------
__device__ float g_xw_a[NN * HH];
__device__ float g_xw_b[NN * HH];
__device__ float g_h[NN * 2 * HH];
__device__ float g_xw_l[NN * CO];
__device__ float g_w0hi[K0PAD * 128], g_w0lo[K0PAD * 128];  // [k][col], cols=[Wst|Wts]
__device__ float g_w1hi[128 * 128],  g_w1lo[128 * 128];
__device__ int   g_degi_st[NN], g_degi_ts[NN];
__device__ int   g_degtot[NN];
__device__ int   g_rowstart[NN + 1];
__device__ int   g_cursor[NN];
__device__ int   g_bsum[SCAN_B];
__device__ int   g_boff[SCAN_B];
__device__ int   g_src_sorted[EE];
__device__ float g_cdir_sorted[EE];   // sign encodes branch: + => st (xw_a), - => ts (xw_b)
__device__ float g_call_sorted[EE];
__device__ float g_dinv_st[NN], g_dinv_ts[NN], g_dinv_all[NN];
__device__ int   g_flags[2];          // [0]=saw_float_bits, [1]=saw_byte_layout

// ---------------- helpers ----------------
__device__ __forceinline__ int edge_reversed(const void* m, int e) {
    if (g_flags[1]) return ((const unsigned char*)m)[e] != 0;
    if (g_flags[0]) return ((const float*)m)[e] != 0.0f;
    return ((const int*)m)[e] != 0;
}

__device__ __forceinline__ uint32_t f2tf32(float f) {
    uint32_t r;
    asm("cvt.rna.tf32.f32 %0, %1;" : "=r"(r) : "f"(f));
    return r;
}

__device__ __forceinline__ void mma_tf32(float* c, const uint32_t* a, const uint32_t* b) {
    asm volatile("mma.sync.aligned.m16n8k8.row.col.f32.tf32.tf32.f32 "
                 "{%0,%1,%2,%3}, {%4,%5,%6,%7}, {%8,%9}, {%0,%1,%2,%3};"
                 : "+f"(c[0]), "+f"(c[1]), "+f"(c[2]), "+f"(c[3])
                 : "r"(a[0]), "r"(a[1]), "r"(a[2]), "r"(a[3]), "r"(b[0]), "r"(b[1]));
}

// ---------------- prep: zero degree arrays + probe is_reversed layout ----------------
__global__ void k_prep(const unsigned int* __restrict__ m) {
    int i = blockIdx.x * blockDim.x + threadIdx.x;
    if (i < NN) { g_degi_st[i] = 0; g_degi_ts[i] = 0; }
    if (i < 2) g_flags[i] = 0;
    unsigned int sawF = 0, sawB = 0;
    if (i < 200000) {
        unsigned int w = m[i];
        if (w > 1u) { if (w == 0x3F800000u) sawF = 1; else sawB = 1; }
    }
    sawF = __any_sync(0xFFFFFFFF, sawF);
    sawB = __any_sync(0xFFFFFFFF, sawB);
    if ((threadIdx.x & 31) == 0) {
        if (sawF) atomicOr(&g_flags[0], 1);
        if (sawB) atomicOr(&g_flags[1], 1);
    }
}

// ---------------- degree histogram ----------------
__global__ void k_hist(const int* __restrict__ dst, const void* __restrict__ mrev) {
    int e = blockIdx.x * blockDim.x + threadIdx.x;
    if (e >= EE) return;
    int d = dst[e];
    if (edge_reversed(mrev, e)) atomicAdd(&g_degi_ts[d], 1);
    else                        atomicAdd(&g_degi_st[d], 1);
}

// ---------------- pre-split weights into tf32 hi/lo planes ----------------
__global__ void k_wsplit(const float* __restrict__ W_st0, const float* __restrict__ W_ts0,
                         const float* __restrict__ W_st1, const float* __restrict__ W_ts1) {
    int i = blockIdx.x * blockDim.x + threadIdx.x;
    if (i < K0PAD * 128) {
        int k = i >> 7, c = i & 127;
        float f = 0.f;
        if (k < FIN) f = (c < 64) ? W_st0[k * 64 + c] : W_ts0[k * 64 + (c - 64)];
        uint32_t hi = f2tf32(f);
        float fh = __uint_as_float(hi);
        g_w0hi[i] = fh;
        g_w0lo[i] = __uint_as_float(f2tf32(f - fh));
    }
    if (i < 128 * 128) {
        int k = i >> 7, c = i & 127;
        float f = (c < 64) ? W_st1[k * 64 + c] : W_ts1[k * 64 + (c - 64)];
        uint32_t hi = f2tf32(f);
        float fh = __uint_as_float(hi);
        g_w1hi[i] = fh;
        g_w1lo[i] = __uint_as_float(f2tf32(f - fh));
    }
}

__global__ void k_dinv() {
    int n = blockIdx.x * blockDim.x + threadIdx.x;
    if (n >= NN) return;
    int ids = g_degi_st[n], idt = g_degi_ts[n];
    float ds = (float)ids, dt = (float)idt;
    g_degtot[n] = ids + idt;
    g_dinv_st[n]  = rsqrtf(ds + 1.f);
    g_dinv_ts[n]  = rsqrtf(dt + 1.f);
    g_dinv_all[n] = rsqrtf(ds + dt + 1.f);
}

// ---------------- two-level exclusive scan of degtot -> rowstart ----------------
__global__ __launch_bounds__(1024)
void k_scan1() {
    int b = blockIdx.x, t = threadIdx.x;
    int i = b * 1024 + t;
    int v = (i < NN) ? g_degtot[i] : 0;
    int lane = t & 31, wid = t >> 5;
    int x = v;
#pragma unroll
    for (int o = 1; o < 32; o <<= 1) {
        int u = __shfl_up_sync(0xFFFFFFFF, x, o);
        if (lane >= o) x += u;
    }
    __shared__ int ws[32];
    if (lane == 31) ws[wid] = x;
    __syncthreads();
    if (wid == 0) {
        int s = ws[lane];
#pragma unroll
        for (int o = 1; o < 32; o <<= 1) {
            int u = __shfl_up_sync(0xFFFFFFFF, s, o);
            if (lane >= o) s += u;
        }
        ws[lane] = s;
    }
    __syncthreads();
    int incl = x + (wid > 0 ? ws[wid - 1] : 0);
    if (i < NN) g_rowstart[i] = incl - v;
    if (t == 1023) g_bsum[b] = incl;
}

__global__ __launch_bounds__(64)
void k_scan2() {
    int t = threadIdx.x;
    int v = (t < SCAN_B) ? g_bsum[t] : 0;
    int lane = t & 31, wid = t >> 5;
    int x = v;
#pragma unroll
    for (int o = 1; o < 32; o <<= 1) {
        int u = __shfl_up_sync(0xFFFFFFFF, x, o);
        if (lane >= o) x += u;
    }
    __shared__ int w0;
    if (wid == 0 && lane == 31) w0 = x;
    __syncthreads();
    int incl = x + (wid == 1 ? w0 : 0);
    if (t < SCAN_B) g_boff[t] = incl - v;
}

__global__ __launch_bounds__(1024)
void k_scan3() {
    int b = blockIdx.x, t = threadIdx.x;
    int i = b * 1024 + t;
    if (i < NN) {
        int r = g_rowstart[i] + g_boff[b];
        g_rowstart[i] = r;
        g_cursor[i] = r;
    }
    if (i == 0) g_rowstart[NN] = EE;
}

// ---------------- fill CSR buckets ----------------
__global__ void k_fill(const int* __restrict__ src, const int* __restrict__ dst,
                       const void* __restrict__ mrev) {
    int e = blockIdx.x * blockDim.x + threadIdx.x;
    if (e >= EE) return;
    int s = src[e], d = dst[e];
    int rev = edge_reversed(mrev, e);
    int pos = atomicAdd(&g_cursor[d], 1);
    float c = rev ? (g_dinv_ts[s] * g_dinv_ts[d]) : (g_dinv_st[s] * g_dinv_st[d]);
    g_src_sorted[pos]  = s;
    g_cdir_sorted[pos] = rev ? -c : c;
    g_call_sorted[pos] = g_dinv_all[s] * g_dinv_all[d];
}

// ---------------- tensor-core GEMM: C[M,128] = A[M,K] @ [Wa | Wb] -------------
// tf32 mma.m16n8k8, 2-term split, hi/lo hoisted out of the consumer loop:
// weights pre-split in global; A split once in the loader. Consumers: LDS + mma only.
// 8 warps = 4(m) x 2(n); warp tile 32x64 = 2 m-tiles x 8 n-tiles.
__global__ __launch_bounds__(256)
void k_gemm_tc(const float* __restrict__ Aparam, int M, int K, int lsel, int asel) {
    const float* A  = asel ? g_h : Aparam;
    const float* WH = lsel ? g_w1hi : g_w0hi;
    const float* WL = lsel ? g_w1lo : g_w0lo;
    __shared__ float sAh[2][128 * 8], sAl[2][128 * 8];
    __shared__ float sBh[2][8 * BSTRIDE], sBl[2][8 * BSTRIDE];
    int tid = threadIdx.x;
    int wid = tid >> 5, lane = tid & 31;
    int wm = wid >> 1, wn = wid & 1;
    int tq = lane >> 2, tr = lane & 3;
    int bm = blockIdx.x * 128;

    // gmem->smem mapping
    int ar = tid >> 1, ac = (tid & 1) * 4;   // A: row 0..127, col-group 0/4
    int bkrow = tid >> 5;                    // B: k-row 0..7
    int bcol = lane * 4;                     // B: col 0..124

    int agrow = bm + ar;
    bool arow_ok = agrow < M;
    const float* Abase = A + (size_t)agrow * K + ac;

    float acc[2][8][4];
#pragma unroll
    for (int mt = 0; mt < 2; mt++)
#pragma unroll
        for (int nt = 0; nt < 8; nt++)
#pragma unroll
            for (int j = 0; j < 4; j++) acc[mt][nt][j] = 0.f;

    int nch = (K + 7) / 8;

    // prologue: chunk 0 -> buf 0
    {
        float4 av = make_float4(0.f, 0.f, 0.f, 0.f);
        if (arow_ok && ac < K) av = *(const float4*)(Abase);
        float4 ah, al;
        ah.x = __uint_as_float(f2tf32(av.x)); al.x = __uint_as_float(f2tf32(av.x - ah.x));
        ah.y = __uint_as_float(f2tf32(av.y)); al.y = __uint_as_float(f2tf32(av.y - ah.y));
        ah.z = __uint_as_float(f2tf32(av.z)); al.z = __uint_as_float(f2tf32(av.z - ah.z));
        ah.w = __uint_as_float(f2tf32(av.w)); al.w = __uint_as_float(f2tf32(av.w - ah.w));
        *(float4*)&sAh[0][ar * 8 + ac] = ah;
        *(float4*)&sAl[0][ar * 8 + ac] = al;
        float4 bh = *(const float4*)(WH + bkrow * 128 + bcol);
        float4 bl = *(const float4*)(WL + bkrow * 128 + bcol);
        *(float4*)&sBh[0][bkrow * BSTRIDE + bcol] = bh;
        *(float4*)&sBl[0][bkrow * BSTRIDE + bcol] = bl;
    }
    __syncthreads();

    int buf = 0;
    for (int ch = 0; ch < nch; ch++) {
        int kn = (ch + 1) * 8;
        float4 av2 = make_float4(0.f, 0.f, 0.f, 0.f);
        float4 bh2 = make_float4(0.f, 0.f, 0.f, 0.f);
        float4 bl2 = make_float4(0.f, 0.f, 0.f, 0.f);
        if (ch + 1 < nch) {
            int gk = kn + ac;
            if (arow_ok && gk < K) av2 = *(const float4*)(Abase + kn);
            int bk = kn + bkrow;   // weight planes are zero-padded to nch*8 rows
            bh2 = *(const float4*)(WH + bk * 128 + bcol);
            bl2 = *(const float4*)(WL + bk * 128 + bcol);
        }

        // A fragments (2 m-tiles): pure LDS, pre-split
        uint32_t ahi[2][4], alo[2][4];
#pragma unroll
        for (int mt = 0; mt < 2; mt++) {
            int rb = wm * 32 + mt * 16;
#pragma unroll
            for (int j = 0; j < 4; j++) {
                int row = rb + tq + (j & 1) * 8;
                int col = tr + (j >> 1) * 4;
                ahi[mt][j] = __float_as_uint(sAh[buf][row * 8 + col]);
                alo[mt][j] = __float_as_uint(sAl[buf][row * 8 + col]);
            }
        }

#pragma unroll
        for (int nt = 0; nt < 8; nt++) {
            int cb = wn * 64 + nt * 8 + tq;
            uint32_t bhi[2], blo[2];
            bhi[0] = __float_as_uint(sBh[buf][tr * BSTRIDE + cb]);
            bhi[1] = __float_as_uint(sBh[buf][(tr + 4) * BSTRIDE + cb]);
            blo[0] = __float_as_uint(sBl[buf][tr * BSTRIDE + cb]);
            blo[1] = __float_as_uint(sBl[buf][(tr + 4) * BSTRIDE + cb]);
#pragma unroll
            for (int mt = 0; mt < 2; mt++) {
                mma_tf32(acc[mt][nt], ahi[mt], bhi);
                mma_tf32(acc[mt][nt], ahi[mt], blo);
                mma_tf32(acc[mt][nt], alo[mt], bhi);
            }
        }

        if (ch + 1 < nch) {
            int nb = buf ^ 1;
            float4 ah, al;
            ah.x = __uint_as_float(f2tf32(av2.x)); al.x = __uint_as_float(f2tf32(av2.x - ah.x));
            ah.y = __uint_as_float(f2tf32(av2.y)); al.y = __uint_as_float(f2tf32(av2.y - ah.y));
            ah.z = __uint_as_float(f2tf32(av2.z)); al.z = __uint_as_float(f2tf32(av2.z - ah.z));
            ah.w = __uint_as_float(f2tf32(av2.w)); al.w = __uint_as_float(f2tf32(av2.w - ah.w));
            *(float4*)&sAh[nb][ar * 8 + ac] = ah;
            *(float4*)&sAl[nb][ar * 8 + ac] = al;
            *(float4*)&sBh[nb][bkrow * BSTRIDE + bcol] = bh2;
            *(float4*)&sBl[nb][bkrow * BSTRIDE + bcol] = bl2;
            __syncthreads();
            buf = nb;
        }
    }

    // store: wn==0 -> g_xw_a cols 0..63 ; wn==1 -> g_xw_b cols 0..63
    float* C = wn ? g_xw_b : g_xw_a;
#pragma unroll
    for (int mt = 0; mt < 2; mt++) {
        int row0 = bm + wm * 32 + mt * 16 + tq;
#pragma unroll
        for (int nt = 0; nt < 8; nt++) {
            int col = nt * 8 + tr * 2;
            if (row0 < M)
                *(float2*)(C + (size_t)row0 * 64 + col) = make_float2(acc[mt][nt][0], acc[mt][nt][1]);
            if (row0 + 8 < M)
                *(float2*)(C + (size_t)(row0 + 8) * 64 + col) = make_float2(acc[mt][nt][2], acc[mt][nt][3]);
        }
    }
}

// ---------------- gather aggregation + combine + relu -> h ----------------
__global__ __launch_bounds__(64)
void k_gather64(const float* __restrict__ b_st, const float* __restrict__ b_ts) {
    int n = blockIdx.x;
    int c = threadIdx.x;
    int rs = g_rowstart[n], re = g_rowstart[n + 1];
    float acc_a = 0.f, acc_b = 0.f;
    int i = rs;
    for (; i + 3 < re; i += 4) {
        int   s0 = g_src_sorted[i],   s1 = g_src_sorted[i+1];
        int   s2 = g_src_sorted[i+2], s3 = g_src_sorted[i+3];
        float c0 = g_cdir_sorted[i],   c1 = g_cdir_sorted[i+1];
        float c2 = g_cdir_sorted[i+2], c3 = g_cdir_sorted[i+3];
        float v0 = (c0 >= 0.f) ? g_xw_a[s0 * 64 + c] : g_xw_b[s0 * 64 + c];
        float v1 = (c1 >= 0.f) ? g_xw_a[s1 * 64 + c] : g_xw_b[s1 * 64 + c];
        float v2 = (c2 >= 0.f) ? g_xw_a[s2 * 64 + c] : g_xw_b[s2 * 64 + c];
        float v3 = (c3 >= 0.f) ? g_xw_a[s3 * 64 + c] : g_xw_b[s3 * 64 + c];
        if (c0 >= 0.f) acc_a = fmaf(c0, v0, acc_a); else acc_b = fmaf(-c0, v0, acc_b);
        if (c1 >= 0.f) acc_a = fmaf(c1, v1, acc_a); else acc_b = fmaf(-c1, v1, acc_b);
        if (c2 >= 0.f) acc_a = fmaf(c2, v2, acc_a); else acc_b = fmaf(-c2, v2, acc_b);
        if (c3 >= 0.f) acc_a = fmaf(c3, v3, acc_a); else acc_b = fmaf(-c3, v3, acc_b);
    }
    for (; i < re; i++) {
        int   s0 = g_src_sorted[i];
        float c0 = g_cdir_sorted[i];
        float v0 = (c0 >= 0.f) ? g_xw_a[s0 * 64 + c] : g_xw_b[s0 * 64 + c];
        if (c0 >= 0.f) acc_a = fmaf(c0, v0, acc_a); else acc_b = fmaf(-c0, v0, acc_b);
    }
    float da = g_dinv_st[n], db = g_dinv_ts[n];
    float va = acc_a + g_xw_a[n * 64 + c] * da * da + b_st[c];
    float vb = acc_b + g_xw_b[n * 64 + c] * db * db + b_ts[c];
    g_h[n * 128 + c]      = fmaxf(va, 0.f);
    g_h[n * 128 + 64 + c] = fmaxf(vb, 0.f);
}

// ---------------- last layer: xw_l = h @ W_last ----------------
__global__ void k_gemm16(const float* __restrict__ Wl) {
    __shared__ float Ws[128 * 16];
    for (int i = threadIdx.x; i < 128 * 16; i += blockDim.x) Ws[i] = Wl[i];
    __syncthreads();
    int idx = blockIdx.x * blockDim.x + threadIdx.x;
    int n = idx >> 4;
    int j = idx & 15;
    if (n >= NN) return;
    const float* hr = g_h + (size_t)n * 128;
    float acc = 0.f;
#pragma unroll
    for (int k = 0; k < 128; k++) acc = fmaf(hr[k], Ws[k * 16 + j], acc);
    g_xw_l[n * 16 + j] = acc;
}

// ---------------- final gather + combine + log_softmax -> out ----------------
__global__ __launch_bounds__(128)
void k_gather16_final(const float* __restrict__ b_last, float* __restrict__ out) {
    int lid = threadIdx.x & 15;
    int grp = threadIdx.x >> 4;
    int n = blockIdx.x * 8 + grp;
    int rs = g_rowstart[n], re = g_rowstart[n + 1];
    float acc = 0.f;
    int i = rs;
    for (; i + 1 < re; i += 2) {
        int   s0 = g_src_sorted[i],  s1 = g_src_sorted[i+1];
        float f0 = g_call_sorted[i], f1 = g_call_sorted[i+1];
        acc = fmaf(f0, g_xw_l[s0 * 16 + lid], acc);
        acc = fmaf(f1, g_xw_l[s1 * 16 + lid], acc);
    }
    if (i < re) acc = fmaf(g_call_sorted[i], g_xw_l[g_src_sorted[i] * 16 + lid], acc);
    float dinv = g_dinv_all[n];
    float v = acc + g_xw_l[n * 16 + lid] * dinv * dinv + b_last[lid];
    float m = v;
#pragma unroll
    for (int o = 8; o > 0; o >>= 1) m = fmaxf(m, __shfl_xor_sync(0xFFFFFFFF, m, o, 16));
    float ex = expf(v - m);
    float ssum = ex;
#pragma unroll
    for (int o = 8; o > 0; o >>= 1) ssum += __shfl_xor_sync(0xFFFFFFFF, ssum, o, 16);
    out[n * 16 + lid] = v - (logf(ssum) + m);
}

// ---------------- launch ----------------
extern "C" void kernel_launch(void* const* d_in, const int* in_sizes, int n_in,
                              void* d_out, int out_size) {
    const float* x      = (const float*)d_in[0];
    const int*   ei     = (const int*)d_in[1];
    const void*  mrev   = d_in[2];
    const float* W_st0  = (const float*)d_in[3];
    const float* b_st0  = (const float*)d_in[4];
    const float* W_ts0  = (const float*)d_in[5];
    const float* b_ts0  = (const float*)d_in[6];
    const float* W_st1  = (const float*)d_in[7];
    const float* b_st1  = (const float*)d_in[8];
    const float* W_ts1  = (const float*)d_in[9];
    const float* b_ts1  = (const float*)d_in[10];
    const float* W_last = (const float*)d_in[11];
    const float* b_last = (const float*)d_in[12];
    float* out = (float*)d_out;

    const int* srcp = ei;
    const int* dstp = ei + EE;
    const int TB = 256;
    const int GEMM_BLOCKS = (NN + 127) / 128;

    // launches 0-2
    k_prep<<<(200000 + TB - 1) / TB, TB>>>((const unsigned int*)mrev);
    k_hist<<<(EE + TB - 1) / TB, TB>>>(dstp, mrev);
    k_wsplit<<<(K0PAD * 128 + TB - 1) / TB, TB>>>(W_st0, W_ts0, W_st1, W_ts1);

    // launch 3: tf32 hoisted-split GEMM L0 (profiled slot)
    k_gemm_tc<<<GEMM_BLOCKS, 256>>>(x, NN, FIN, 0, 0);

    // CSR build
    k_dinv<<<(NN + TB - 1) / TB, TB>>>();
    k_scan1<<<SCAN_B, 1024>>>();
    k_scan2<<<1, 64>>>();
    k_scan3<<<SCAN_B, 1024>>>();
    k_fill<<<(EE + TB - 1) / TB, TB>>>(srcp, dstp, mrev);

    // layer 0 aggregation
    k_gather64<<<NN, 64>>>(b_st0, b_ts0);

    // layer 1
    k_gemm_tc<<<GEMM_BLOCKS, 256>>>(nullptr, NN, 2 * HH, 1, 1);
    k_gather64<<<NN, 64>>>(b_st1, b_ts1);

    // last layer
    k_gemm16<<<(NN * 16) / TB, TB>>>(W_last);
    k_gather16_final<<<NN / 8, 128>>>(b_last, out);
}

// round 14
// speedup vs baseline: 1.0026x; 1.0026x over previous
#include <cuda_runtime.h>
#include <cstdint>

#define NN 50000
#define EE 800000
#define FIN 500
#define HH 64
#define CO 16
#define SCAN_B 49     // ceil(NN/1024)
#define BSTRIDE 136   // B smem row stride in floats
#define K0PAD 504     // FIN padded to multiple of 8

// ---------------- scratch (device globals; allocation-free) ----------------
__device__ float g_xw_a[NN * HH];
__device__ float g_xw_b[NN * HH];
__device__ float g_h[NN * 2 * HH];
__device__ float g_xw_l[NN * CO];
__device__ float g_w0hi[K0PAD * 128], g_w0lo[K0PAD * 128];  // [k][col], cols=[Wst|Wts]
__device__ float g_w1hi[128 * 128],  g_w1lo[128 * 128];
__device__ int   g_degi_st[NN], g_degi_ts[NN];
__device__ int   g_degtot[NN];
__device__ int   g_rowstart[NN + 1];
__device__ int   g_cursor[NN];
__device__ int   g_bsum[SCAN_B];
__device__ int   g_boff[SCAN_B];
__device__ int   g_src_sorted[EE];
__device__ float g_cdir_sorted[EE];   // sign encodes branch: + => st (xw_a), - => ts (xw_b)
__device__ float g_call_sorted[EE];
__device__ float g_dinv_st[NN], g_dinv_ts[NN], g_dinv_all[NN];
__device__ int   g_flags[2];          // [0]=saw_float_bits, [1]=saw_byte_layout

// ---------------- helpers ----------------
__device__ __forceinline__ int edge_reversed(const void* m, int e) {
    if (g_flags[1]) return ((const unsigned char*)m)[e] != 0;
    if (g_flags[0]) return ((const float*)m)[e] != 0.0f;
    return ((const int*)m)[e] != 0;
}

__device__ __forceinline__ uint32_t f2tf32(float f) {
    uint32_t r;
    asm("cvt.rna.tf32.f32 %0, %1;" : "=r"(r) : "f"(f));
    return r;
}

__device__ __forceinline__ void mma_tf32(float* c, const uint32_t* a, const uint32_t* b) {
    asm volatile("mma.sync.aligned.m16n8k8.row.col.f32.tf32.tf32.f32 "
                 "{%0,%1,%2,%3}, {%4,%5,%6,%7}, {%8,%9}, {%0,%1,%2,%3};"
                 : "+f"(c[0]), "+f"(c[1]), "+f"(c[2]), "+f"(c[3])
                 : "r"(a[0]), "r"(a[1]), "r"(a[2]), "r"(a[3]), "r"(b[0]), "r"(b[1]));
}

// ---------------- prep: zero degree arrays + probe is_reversed layout ----------------
__global__ void k_prep(const unsigned int* __restrict__ m) {
    int i = blockIdx.x * blockDim.x + threadIdx.x;
    if (i < NN) { g_degi_st[i] = 0; g_degi_ts[i] = 0; }
    if (i < 2) g_flags[i] = 0;
    unsigned int sawF = 0, sawB = 0;
    if (i < 200000) {
        unsigned int w = m[i];
        if (w > 1u) { if (w == 0x3F800000u) sawF = 1; else sawB = 1; }
    }
    sawF = __any_sync(0xFFFFFFFF, sawF);
    sawB = __any_sync(0xFFFFFFFF, sawB);
    if ((threadIdx.x & 31) == 0) {
        if (sawF) atomicOr(&g_flags[0], 1);
        if (sawB) atomicOr(&g_flags[1], 1);
    }
}

// ---------------- degree histogram ----------------
__global__ void k_hist(const int* __restrict__ dst, const void* __restrict__ mrev) {
    int e = blockIdx.x * blockDim.x + threadIdx.x;
    if (e >= EE) return;
    int d = dst[e];
    if (edge_reversed(mrev, e)) atomicAdd(&g_degi_ts[d], 1);
    else                        atomicAdd(&g_degi_st[d], 1);
}

// ---------------- pre-split weights into tf32 hi/lo planes ----------------
__global__ void k_wsplit(const float* __restrict__ W_st0, const float* __restrict__ W_ts0,
                         const float* __restrict__ W_st1, const float* __restrict__ W_ts1) {
    int i = blockIdx.x * blockDim.x + threadIdx.x;
    if (i < K0PAD * 128) {
        int k = i >> 7, c = i & 127;
        float f = 0.f;
        if (k < FIN) f = (c < 64) ? W_st0[k * 64 + c] : W_ts0[k * 64 + (c - 64)];
        uint32_t hi = f2tf32(f);
        float fh = __uint_as_float(hi);
        g_w0hi[i] = fh;
        g_w0lo[i] = __uint_as_float(f2tf32(f - fh));
    }
    if (i < 128 * 128) {
        int k = i >> 7, c = i & 127;
        float f = (c < 64) ? W_st1[k * 64 + c] : W_ts1[k * 64 + (c - 64)];
        uint32_t hi = f2tf32(f);
        float fh = __uint_as_float(hi);
        g_w1hi[i] = fh;
        g_w1lo[i] = __uint_as_float(f2tf32(f - fh));
    }
}

__global__ void k_dinv() {
    int n = blockIdx.x * blockDim.x + threadIdx.x;
    if (n >= NN) return;
    int ids = g_degi_st[n], idt = g_degi_ts[n];
    float ds = (float)ids, dt = (float)idt;
    g_degtot[n] = ids + idt;
    g_dinv_st[n]  = rsqrtf(ds + 1.f);
    g_dinv_ts[n]  = rsqrtf(dt + 1.f);
    g_dinv_all[n] = rsqrtf(ds + dt + 1.f);
}

// ---------------- two-level exclusive scan of degtot -> rowstart ----------------
__global__ __launch_bounds__(1024)
void k_scan1() {
    int b = blockIdx.x, t = threadIdx.x;
    int i = b * 1024 + t;
    int v = (i < NN) ? g_degtot[i] : 0;
    int lane = t & 31, wid = t >> 5;
    int x = v;
#pragma unroll
    for (int o = 1; o < 32; o <<= 1) {
        int u = __shfl_up_sync(0xFFFFFFFF, x, o);
        if (lane >= o) x += u;
    }
    __shared__ int ws[32];
    if (lane == 31) ws[wid] = x;
    __syncthreads();
    if (wid == 0) {
        int s = ws[lane];
#pragma unroll
        for (int o = 1; o < 32; o <<= 1) {
            int u = __shfl_up_sync(0xFFFFFFFF, s, o);
            if (lane >= o) s += u;
        }
        ws[lane] = s;
    }
    __syncthreads();
    int incl = x + (wid > 0 ? ws[wid - 1] : 0);
    if (i < NN) g_rowstart[i] = incl - v;
    if (t == 1023) g_bsum[b] = incl;
}

__global__ __launch_bounds__(64)
void k_scan2() {
    int t = threadIdx.x;
    int v = (t < SCAN_B) ? g_bsum[t] : 0;
    int lane = t & 31, wid = t >> 5;
    int x = v;
#pragma unroll
    for (int o = 1; o < 32; o <<= 1) {
        int u = __shfl_up_sync(0xFFFFFFFF, x, o);
        if (lane >= o) x += u;
    }
    __shared__ int w0;
    if (wid == 0 && lane == 31) w0 = x;
    __syncthreads();
    int incl = x + (wid == 1 ? w0 : 0);
    if (t < SCAN_B) g_boff[t] = incl - v;
}

__global__ __launch_bounds__(1024)
void k_scan3() {
    int b = blockIdx.x, t = threadIdx.x;
    int i = b * 1024 + t;
    if (i < NN) {
        int r = g_rowstart[i] + g_boff[b];
        g_rowstart[i] = r;
        g_cursor[i] = r;
    }
    if (i == 0) g_rowstart[NN] = EE;
}

// ---------------- fill CSR buckets ----------------
__global__ void k_fill(const int* __restrict__ src, const int* __restrict__ dst,
                       const void* __restrict__ mrev) {
    int e = blockIdx.x * blockDim.x + threadIdx.x;
    if (e >= EE) return;
    int s = src[e], d = dst[e];
    int rev = edge_reversed(mrev, e);
    int pos = atomicAdd(&g_cursor[d], 1);
    float c = rev ? (g_dinv_ts[s] * g_dinv_ts[d]) : (g_dinv_st[s] * g_dinv_st[d]);
    g_src_sorted[pos]  = s;
    g_cdir_sorted[pos] = rev ? -c : c;
    g_call_sorted[pos] = g_dinv_all[s] * g_dinv_all[d];
}

// ---------------- tensor-core GEMM: C[M,128] = A[M,K] @ [Wa | Wb] -------------
// tf32 mma.m16n8k8, 2-term split, hoisted hi/lo; consumer restructured into
// three mma passes (hi*hi, hi*lo, lo*hi) so consecutive mmas hit DIFFERENT
// accumulators (RAW reuse distance 16 instead of 1).
// 8 warps = 4(m) x 2(n); warp tile 32x64 = 2 m-tiles x 8 n-tiles.
__global__ __launch_bounds__(256)
void k_gemm_tc(const float* __restrict__ Aparam, int M, int K, int lsel, int asel) {
    const float* A  = asel ? g_h : Aparam;
    const float* WH = lsel ? g_w1hi : g_w0hi;
    const float* WL = lsel ? g_w1lo : g_w0lo;
    __shared__ float sAh[2][128 * 8], sAl[2][128 * 8];
    __shared__ float sBh[2][8 * BSTRIDE], sBl[2][8 * BSTRIDE];
    int tid = threadIdx.x;
    int wid = tid >> 5, lane = tid & 31;
    int wm = wid >> 1, wn = wid & 1;
    int tq = lane >> 2, tr = lane & 3;
    int bm = blockIdx.x * 128;

    // gmem->smem mapping
    int ar = tid >> 1, ac = (tid & 1) * 4;   // A: row 0..127, col-group 0/4
    int bkrow = tid >> 5;                    // B: k-row 0..7
    int bcol = lane * 4;                     // B: col 0..124

    int agrow = bm + ar;
    bool arow_ok = agrow < M;
    const float* Abase = A + (size_t)agrow * K + ac;

    float acc[2][8][4];
#pragma unroll
    for (int mt = 0; mt < 2; mt++)
#pragma unroll
        for (int nt = 0; nt < 8; nt++)
#pragma unroll
            for (int j = 0; j < 4; j++) acc[mt][nt][j] = 0.f;

    int nch = (K + 7) / 8;

    // prologue: chunk 0 -> buf 0
    {
        float4 av = make_float4(0.f, 0.f, 0.f, 0.f);
        if (arow_ok && ac < K) av = *(const float4*)(Abase);
        float4 ah, al;
        ah.x = __uint_as_float(f2tf32(av.x)); al.x = __uint_as_float(f2tf32(av.x - ah.x));
        ah.y = __uint_as_float(f2tf32(av.y)); al.y = __uint_as_float(f2tf32(av.y - ah.y));
        ah.z = __uint_as_float(f2tf32(av.z)); al.z = __uint_as_float(f2tf32(av.z - ah.z));
        ah.w = __uint_as_float(f2tf32(av.w)); al.w = __uint_as_float(f2tf32(av.w - ah.w));
        *(float4*)&sAh[0][ar * 8 + ac] = ah;
        *(float4*)&sAl[0][ar * 8 + ac] = al;
        float4 bh = *(const float4*)(WH + bkrow * 128 + bcol);
        float4 bl = *(const float4*)(WL + bkrow * 128 + bcol);
        *(float4*)&sBh[0][bkrow * BSTRIDE + bcol] = bh;
        *(float4*)&sBl[0][bkrow * BSTRIDE + bcol] = bl;
    }
    __syncthreads();

    int buf = 0;
    for (int ch = 0; ch < nch; ch++) {
        int kn = (ch + 1) * 8;
        float4 av2 = make_float4(0.f, 0.f, 0.f, 0.f);
        float4 bh2 = make_float4(0.f, 0.f, 0.f, 0.f);
        float4 bl2 = make_float4(0.f, 0.f, 0.f, 0.f);
        if (ch + 1 < nch) {
            int gk = kn + ac;
            if (arow_ok && gk < K) av2 = *(const float4*)(Abase + kn);
            int bk = kn + bkrow;   // weight planes are zero-padded to nch*8 rows
            bh2 = *(const float4*)(WH + bk * 128 + bcol);
            bl2 = *(const float4*)(WL + bk * 128 + bcol);
        }

        // A fragments (2 m-tiles): pure LDS, pre-split
        uint32_t ahi[2][4], alo[2][4];
#pragma unroll
        for (int mt = 0; mt < 2; mt++) {
            int rb = wm * 32 + mt * 16;
#pragma unroll
            for (int j = 0; j < 4; j++) {
                int row = rb + tq + (j & 1) * 8;
                int col = tr + (j >> 1) * 4;
                ahi[mt][j] = __float_as_uint(sAh[buf][row * 8 + col]);
                alo[mt][j] = __float_as_uint(sAl[buf][row * 8 + col]);
            }
        }

        // B fragments (all 8 n-tiles) loaded up front
        uint32_t bhi[8][2], blo[8][2];
#pragma unroll
        for (int nt = 0; nt < 8; nt++) {
            int cb = wn * 64 + nt * 8 + tq;
            bhi[nt][0] = __float_as_uint(sBh[buf][tr * BSTRIDE + cb]);
            bhi[nt][1] = __float_as_uint(sBh[buf][(tr + 4) * BSTRIDE + cb]);
            blo[nt][0] = __float_as_uint(sBl[buf][tr * BSTRIDE + cb]);
            blo[nt][1] = __float_as_uint(sBl[buf][(tr + 4) * BSTRIDE + cb]);
        }

        // pass 1: hi*hi (16 independent accumulators)
#pragma unroll
        for (int nt = 0; nt < 8; nt++)
#pragma unroll
            for (int mt = 0; mt < 2; mt++)
                mma_tf32(acc[mt][nt], ahi[mt], bhi[nt]);
        // pass 2: hi*lo
#pragma unroll
        for (int nt = 0; nt < 8; nt++)
#pragma unroll
            for (int mt = 0; mt < 2; mt++)
                mma_tf32(acc[mt][nt], ahi[mt], blo[nt]);
        // pass 3: lo*hi
#pragma unroll
        for (int nt = 0; nt < 8; nt++)
#pragma unroll
            for (int mt = 0; mt < 2; mt++)
                mma_tf32(acc[mt][nt], alo[mt], bhi[nt]);

        if (ch + 1 < nch) {
            int nb = buf ^ 1;
            float4 ah, al;
            ah.x = __uint_as_float(f2tf32(av2.x)); al.x = __uint_as_float(f2tf32(av2.x - ah.x));
            ah.y = __uint_as_float(f2tf32(av2.y)); al.y = __uint_as_float(f2tf32(av2.y - ah.y));
            ah.z = __uint_as_float(f2tf32(av2.z)); al.z = __uint_as_float(f2tf32(av2.z - ah.z));
            ah.w = __uint_as_float(f2tf32(av2.w)); al.w = __uint_as_float(f2tf32(av2.w - ah.w));
            *(float4*)&sAh[nb][ar * 8 + ac] = ah;
            *(float4*)&sAl[nb][ar * 8 + ac] = al;
            *(float4*)&sBh[nb][bkrow * BSTRIDE + bcol] = bh2;
            *(float4*)&sBl[nb][bkrow * BSTRIDE + bcol] = bl2;
            __syncthreads();
            buf = nb;
        }
    }

    // store: wn==0 -> g_xw_a cols 0..63 ; wn==1 -> g_xw_b cols 0..63
    float* C = wn ? g_xw_b : g_xw_a;
#pragma unroll
    for (int mt = 0; mt < 2; mt++) {
        int row0 = bm + wm * 32 + mt * 16 + tq;
#pragma unroll
        for (int nt = 0; nt < 8; nt++) {
            int col = nt * 8 + tr * 2;
            if (row0 < M)
                *(float2*)(C + (size_t)row0 * 64 + col) = make_float2(acc[mt][nt][0], acc[mt][nt][1]);
            if (row0 + 8 < M)
                *(float2*)(C + (size_t)(row0 + 8) * 64 + col) = make_float2(acc[mt][nt][2], acc[mt][nt][3]);
        }
    }
}

// ---------------- gather aggregation + combine + relu -> h ----------------
__global__ __launch_bounds__(64)
void k_gather64(const float* __restrict__ b_st, const float* __restrict__ b_ts) {
    int n = blockIdx.x;
    int c = threadIdx.x;
    int rs = g_rowstart[n], re = g_rowstart[n + 1];
    float acc_a = 0.f, acc_b = 0.f;
    int i = rs;
    for (; i + 3 < re; i += 4) {
        int   s0 = g_src_sorted[i],   s1 = g_src_sorted[i+1];
        int   s2 = g_src_sorted[i+2], s3 = g_src_sorted[i+3];
        float c0 = g_cdir_sorted[i],   c1 = g_cdir_sorted[i+1];
        float c2 = g_cdir_sorted[i+2], c3 = g_cdir_sorted[i+3];
        float v0 = (c0 >= 0.f) ? g_xw_a[s0 * 64 + c] : g_xw_b[s0 * 64 + c];
        float v1 = (c1 >= 0.f) ? g_xw_a[s1 * 64 + c] : g_xw_b[s1 * 64 + c];
        float v2 = (c2 >= 0.f) ? g_xw_a[s2 * 64 + c] : g_xw_b[s2 * 64 + c];
        float v3 = (c3 >= 0.f) ? g_xw_a[s3 * 64 + c] : g_xw_b[s3 * 64 + c];
        if (c0 >= 0.f) acc_a = fmaf(c0, v0, acc_a); else acc_b = fmaf(-c0, v0, acc_b);
        if (c1 >= 0.f) acc_a = fmaf(c1, v1, acc_a); else acc_b = fmaf(-c1, v1, acc_b);
        if (c2 >= 0.f) acc_a = fmaf(c2, v2, acc_a); else acc_b = fmaf(-c2, v2, acc_b);
        if (c3 >= 0.f) acc_a = fmaf(c3, v3, acc_a); else acc_b = fmaf(-c3, v3, acc_b);
    }
    for (; i < re; i++) {
        int   s0 = g_src_sorted[i];
        float c0 = g_cdir_sorted[i];
        float v0 = (c0 >= 0.f) ? g_xw_a[s0 * 64 + c] : g_xw_b[s0 * 64 + c];
        if (c0 >= 0.f) acc_a = fmaf(c0, v0, acc_a); else acc_b = fmaf(-c0, v0, acc_b);
    }
    float da = g_dinv_st[n], db = g_dinv_ts[n];
    float va = acc_a + g_xw_a[n * 64 + c] * da * da + b_st[c];
    float vb = acc_b + g_xw_b[n * 64 + c] * db * db + b_ts[c];
    g_h[n * 128 + c]      = fmaxf(va, 0.f);
    g_h[n * 128 + 64 + c] = fmaxf(vb, 0.f);
}

// ---------------- last layer: xw_l = h @ W_last ----------------
__global__ void k_gemm16(const float* __restrict__ Wl) {
    __shared__ float Ws[128 * 16];
    for (int i = threadIdx.x; i < 128 * 16; i += blockDim.x) Ws[i] = Wl[i];
    __syncthreads();
    int idx = blockIdx.x * blockDim.x + threadIdx.x;
    int n = idx >> 4;
    int j = idx & 15;
    if (n >= NN) return;
    const float* hr = g_h + (size_t)n * 128;
    float acc = 0.f;
#pragma unroll
    for (int k = 0; k < 128; k++) acc = fmaf(hr[k], Ws[k * 16 + j], acc);
    g_xw_l[n * 16 + j] = acc;
}

// ---------------- final gather + combine + log_softmax -> out ----------------
__global__ __launch_bounds__(128)
void k_gather16_final(const float* __restrict__ b_last, float* __restrict__ out) {
    int lid = threadIdx.x & 15;
    int grp = threadIdx.x >> 4;
    int n = blockIdx.x * 8 + grp;
    int rs = g_rowstart[n], re = g_rowstart[n + 1];
    float acc = 0.f;
    int i = rs;
    for (; i + 1 < re; i += 2) {
        int   s0 = g_src_sorted[i],  s1 = g_src_sorted[i+1];
        float f0 = g_call_sorted[i], f1 = g_call_sorted[i+1];
        acc = fmaf(f0, g_xw_l[s0 * 16 + lid], acc);
        acc = fmaf(f1, g_xw_l[s1 * 16 + lid], acc);
    }
    if (i < re) acc = fmaf(g_call_sorted[i], g_xw_l[g_src_sorted[i] * 16 + lid], acc);
    float dinv = g_dinv_all[n];
    float v = acc + g_xw_l[n * 16 + lid] * dinv * dinv + b_last[lid];
    float m = v;
#pragma unroll
    for (int o = 8; o > 0; o >>= 1) m = fmaxf(m, __shfl_xor_sync(0xFFFFFFFF, m, o, 16));
    float ex = expf(v - m);
    float ssum = ex;
#pragma unroll
    for (int o = 8; o > 0; o >>= 1) ssum += __shfl_xor_sync(0xFFFFFFFF, ssum, o, 16);
    out[n * 16 + lid] = v - (logf(ssum) + m);
}

// ---------------- launch ----------------
extern "C" void kernel_launch(void* const* d_in, const int* in_sizes, int n_in,
                              void* d_out, int out_size) {
    const float* x      = (const float*)d_in[0];
    const int*   ei     = (const int*)d_in[1];
    const void*  mrev   = d_in[2];
    const float* W_st0  = (const float*)d_in[3];
    const float* b_st0  = (const float*)d_in[4];
    const float* W_ts0  = (const float*)d_in[5];
    const float* b_ts0  = (const float*)d_in[6];
    const float* W_st1  = (const float*)d_in[7];
    const float* b_st1  = (const float*)d_in[8];
    const float* W_ts1  = (const float*)d_in[9];
    const float* b_ts1  = (const float*)d_in[10];
    const float* W_last = (const float*)d_in[11];
    const float* b_last = (const float*)d_in[12];
    float* out = (float*)d_out;

    const int* srcp = ei;
    const int* dstp = ei + EE;
    const int TB = 256;
    const int GEMM_BLOCKS = (NN + 127) / 128;

    // launches 0-2
    k_prep<<<(200000 + TB - 1) / TB, TB>>>((const unsigned int*)mrev);
    k_hist<<<(EE + TB - 1) / TB, TB>>>(dstp, mrev);
    k_wsplit<<<(K0PAD * 128 + TB - 1) / TB, TB>>>(W_st0, W_ts0, W_st1, W_ts1);

    // launch 3: tf32 pipelined-split GEMM L0 (profiled slot)
    k_gemm_tc<<<GEMM_BLOCKS, 256>>>(x, NN, FIN, 0, 0);

    // CSR build
    k_dinv<<<(NN + TB - 1) / TB, TB>>>();
    k_scan1<<<SCAN_B, 1024>>>();
    k_scan2<<<1, 64>>>();
    k_scan3<<<SCAN_B, 1024>>>();
    k_fill<<<(EE + TB - 1) / TB, TB>>>(srcp, dstp, mrev);

    // layer 0 aggregation
    k_gather64<<<NN, 64>>>(b_st0, b_ts0);

    // layer 1
    k_gemm_tc<<<GEMM_BLOCKS, 256>>>(nullptr, NN, 2 * HH, 1, 1);
    k_gather64<<<NN, 64>>>(b_st1, b_ts1);

    // last layer
    k_gemm16<<<(NN * 16) / TB, TB>>>(W_last);
    k_gather16_final<<<NN / 8, 128>>>(b_last, out);
}

// round 15
// speedup vs baseline: 1.0691x; 1.0664x over previous
#include <cuda_runtime.h>
#include <cstdint>

#define NN 50000
#define EE 800000
#define FIN 500
#define HH 64
#define CO 16
#define SCAN_B 49     // ceil(NN/1024)
#define BSTRIDE 136   // B smem row stride in floats
#define K0PAD 504     // FIN padded to multiple of 8

// ---------------- scratch (device globals; allocation-free) ----------------
__device__ float g_xw_a[NN * HH];
__device__ float g_xw_b[NN * HH];
__device__ float g_h[NN * 2 * HH];
__device__ float g_xw_l[NN * CO];
__device__ float g_w0hi[K0PAD * 128], g_w0lo[K0PAD * 128];  // [k][col], cols=[Wst|Wts]
__device__ float g_w1hi[128 * 128],  g_w1lo[128 * 128];
__device__ int   g_degi_st[NN], g_degi_ts[NN];
__device__ int   g_degtot[NN];
__device__ int   g_rowstart[NN + 1];
__device__ int   g_cursor[NN];
__device__ int   g_bsum[SCAN_B];
__device__ int   g_boff[SCAN_B];
__device__ int   g_src_sorted[EE];
__device__ float g_cdir_sorted[EE];   // sign encodes branch: + => st (xw_a), - => ts (xw_b)
__device__ float g_call_sorted[EE];
__device__ float g_dinv_st[NN], g_dinv_ts[NN], g_dinv_all[NN];
__device__ int   g_flags[2];          // [0]=saw_float_bits, [1]=saw_byte_layout

// ---------------- helpers ----------------
__device__ __forceinline__ int edge_reversed(const void* m, int e) {
    if (g_flags[1]) return ((const unsigned char*)m)[e] != 0;
    if (g_flags[0]) return ((const float*)m)[e] != 0.0f;
    return ((const int*)m)[e] != 0;
}

__device__ __forceinline__ uint32_t f2tf32(float f) {
    uint32_t r;
    asm("cvt.rna.tf32.f32 %0, %1;" : "=r"(r) : "f"(f));
    return r;
}

__device__ __forceinline__ void mma_tf32(float* c, const uint32_t* a, const uint32_t* b) {
    asm volatile("mma.sync.aligned.m16n8k8.row.col.f32.tf32.tf32.f32 "
                 "{%0,%1,%2,%3}, {%4,%5,%6,%7}, {%8,%9}, {%0,%1,%2,%3};"
                 : "+f"(c[0]), "+f"(c[1]), "+f"(c[2]), "+f"(c[3])
                 : "r"(a[0]), "r"(a[1]), "r"(a[2]), "r"(a[3]), "r"(b[0]), "r"(b[1]));
}

// ---------------- prep: zero degree arrays + probe is_reversed layout ----------------
__global__ void k_prep(const unsigned int* __restrict__ m) {
    int i = blockIdx.x * blockDim.x + threadIdx.x;
    if (i < NN) { g_degi_st[i] = 0; g_degi_ts[i] = 0; }
    if (i < 2) g_flags[i] = 0;
    unsigned int sawF = 0, sawB = 0;
    if (i < 200000) {
        unsigned int w = m[i];
        if (w > 1u) { if (w == 0x3F800000u) sawF = 1; else sawB = 1; }
    }
    sawF = __any_sync(0xFFFFFFFF, sawF);
    sawB = __any_sync(0xFFFFFFFF, sawB);
    if ((threadIdx.x & 31) == 0) {
        if (sawF) atomicOr(&g_flags[0], 1);
        if (sawB) atomicOr(&g_flags[1], 1);
    }
}

// ---------------- degree histogram ----------------
__global__ void k_hist(const int* __restrict__ dst, const void* __restrict__ mrev) {
    int e = blockIdx.x * blockDim.x + threadIdx.x;
    if (e >= EE) return;
    int d = dst[e];
    if (edge_reversed(mrev, e)) atomicAdd(&g_degi_ts[d], 1);
    else                        atomicAdd(&g_degi_st[d], 1);
}

// ---------------- pre-split weights into tf32 hi/lo planes ----------------
__global__ void k_wsplit(const float* __restrict__ W_st0, const float* __restrict__ W_ts0,
                         const float* __restrict__ W_st1, const float* __restrict__ W_ts1) {
    int i = blockIdx.x * blockDim.x + threadIdx.x;
    if (i < K0PAD * 128) {
        int k = i >> 7, c = i & 127;
        float f = 0.f;
        if (k < FIN) f = (c < 64) ? W_st0[k * 64 + c] : W_ts0[k * 64 + (c - 64)];
        uint32_t hi = f2tf32(f);
        float fh = __uint_as_float(hi);
        g_w0hi[i] = fh;
        g_w0lo[i] = __uint_as_float(f2tf32(f - fh));
    }
    if (i < 128 * 128) {
        int k = i >> 7, c = i & 127;
        float f = (c < 64) ? W_st1[k * 64 + c] : W_ts1[k * 64 + (c - 64)];
        uint32_t hi = f2tf32(f);
        float fh = __uint_as_float(hi);
        g_w1hi[i] = fh;
        g_w1lo[i] = __uint_as_float(f2tf32(f - fh));
    }
}

__global__ void k_dinv() {
    int n = blockIdx.x * blockDim.x + threadIdx.x;
    if (n >= NN) return;
    int ids = g_degi_st[n], idt = g_degi_ts[n];
    float ds = (float)ids, dt = (float)idt;
    g_degtot[n] = ids + idt;
    g_dinv_st[n]  = rsqrtf(ds + 1.f);
    g_dinv_ts[n]  = rsqrtf(dt + 1.f);
    g_dinv_all[n] = rsqrtf(ds + dt + 1.f);
}

// ---------------- two-level exclusive scan of degtot -> rowstart ----------------
__global__ __launch_bounds__(1024)
void k_scan1() {
    int b = blockIdx.x, t = threadIdx.x;
    int i = b * 1024 + t;
    int v = (i < NN) ? g_degtot[i] : 0;
    int lane = t & 31, wid = t >> 5;
    int x = v;
#pragma unroll
    for (int o = 1; o < 32; o <<= 1) {
        int u = __shfl_up_sync(0xFFFFFFFF, x, o);
        if (lane >= o) x += u;
    }
    __shared__ int ws[32];
    if (lane == 31) ws[wid] = x;
    __syncthreads();
    if (wid == 0) {
        int s = ws[lane];
#pragma unroll
        for (int o = 1; o < 32; o <<= 1) {
            int u = __shfl_up_sync(0xFFFFFFFF, s, o);
            if (lane >= o) s += u;
        }
        ws[lane] = s;
    }
    __syncthreads();
    int incl = x + (wid > 0 ? ws[wid - 1] : 0);
    if (i < NN) g_rowstart[i] = incl - v;
    if (t == 1023) g_bsum[b] = incl;
}

__global__ __launch_bounds__(64)
void k_scan2() {
    int t = threadIdx.x;
    int v = (t < SCAN_B) ? g_bsum[t] : 0;
    int lane = t & 31, wid = t >> 5;
    int x = v;
#pragma unroll
    for (int o = 1; o < 32; o <<= 1) {
        int u = __shfl_up_sync(0xFFFFFFFF, x, o);
        if (lane >= o) x += u;
    }
    __shared__ int w0;
    if (wid == 0 && lane == 31) w0 = x;
    __syncthreads();
    int incl = x + (wid == 1 ? w0 : 0);
    if (t < SCAN_B) g_boff[t] = incl - v;
}

__global__ __launch_bounds__(1024)
void k_scan3() {
    int b = blockIdx.x, t = threadIdx.x;
    int i = b * 1024 + t;
    if (i < NN) {
        int r = g_rowstart[i] + g_boff[b];
        g_rowstart[i] = r;
        g_cursor[i] = r;
    }
    if (i == 0) g_rowstart[NN] = EE;
}

// ---------------- fill CSR buckets ----------------
__global__ void k_fill(const int* __restrict__ src, const int* __restrict__ dst,
                       const void* __restrict__ mrev) {
    int e = blockIdx.x * blockDim.x + threadIdx.x;
    if (e >= EE) return;
    int s = src[e], d = dst[e];
    int rev = edge_reversed(mrev, e);
    int pos = atomicAdd(&g_cursor[d], 1);
    float c = rev ? (g_dinv_ts[s] * g_dinv_ts[d]) : (g_dinv_st[s] * g_dinv_st[d]);
    g_src_sorted[pos]  = s;
    g_cdir_sorted[pos] = rev ? -c : c;
    g_call_sorted[pos] = g_dinv_all[s] * g_dinv_all[d];
}

// ---------------- tensor-core GEMM: C[M,128] = A[M,K] @ [Wa | Wb] -------------
// tf32 mma.m16n8k8, 2-term split, hoisted hi/lo; three mma passes per chunk.
// 8 warps = 4(m) x 2(n); warp tile 32x64 = 2 m-tiles x 8 n-tiles.
__global__ __launch_bounds__(256)
void k_gemm_tc(const float* __restrict__ Aparam, int M, int K, int lsel, int asel) {
    const float* A  = asel ? g_h : Aparam;
    const float* WH = lsel ? g_w1hi : g_w0hi;
    const float* WL = lsel ? g_w1lo : g_w0lo;
    __shared__ float sAh[2][128 * 8], sAl[2][128 * 8];
    __shared__ float sBh[2][8 * BSTRIDE], sBl[2][8 * BSTRIDE];
    int tid = threadIdx.x;
    int wid = tid >> 5, lane = tid & 31;
    int wm = wid >> 1, wn = wid & 1;
    int tq = lane >> 2, tr = lane & 3;
    int bm = blockIdx.x * 128;

    int ar = tid >> 1, ac = (tid & 1) * 4;
    int bkrow = tid >> 5;
    int bcol = lane * 4;

    int agrow = bm + ar;
    bool arow_ok = agrow < M;
    const float* Abase = A + (size_t)agrow * K + ac;

    float acc[2][8][4];
#pragma unroll
    for (int mt = 0; mt < 2; mt++)
#pragma unroll
        for (int nt = 0; nt < 8; nt++)
#pragma unroll
            for (int j = 0; j < 4; j++) acc[mt][nt][j] = 0.f;

    int nch = (K + 7) / 8;

    {
        float4 av = make_float4(0.f, 0.f, 0.f, 0.f);
        if (arow_ok && ac < K) av = *(const float4*)(Abase);
        float4 ah, al;
        ah.x = __uint_as_float(f2tf32(av.x)); al.x = __uint_as_float(f2tf32(av.x - ah.x));
        ah.y = __uint_as_float(f2tf32(av.y)); al.y = __uint_as_float(f2tf32(av.y - ah.y));
        ah.z = __uint_as_float(f2tf32(av.z)); al.z = __uint_as_float(f2tf32(av.z - ah.z));
        ah.w = __uint_as_float(f2tf32(av.w)); al.w = __uint_as_float(f2tf32(av.w - ah.w));
        *(float4*)&sAh[0][ar * 8 + ac] = ah;
        *(float4*)&sAl[0][ar * 8 + ac] = al;
        float4 bh = *(const float4*)(WH + bkrow * 128 + bcol);
        float4 bl = *(const float4*)(WL + bkrow * 128 + bcol);
        *(float4*)&sBh[0][bkrow * BSTRIDE + bcol] = bh;
        *(float4*)&sBl[0][bkrow * BSTRIDE + bcol] = bl;
    }
    __syncthreads();

    int buf = 0;
    for (int ch = 0; ch < nch; ch++) {
        int kn = (ch + 1) * 8;
        float4 av2 = make_float4(0.f, 0.f, 0.f, 0.f);
        float4 bh2 = make_float4(0.f, 0.f, 0.f, 0.f);
        float4 bl2 = make_float4(0.f, 0.f, 0.f, 0.f);
        if (ch + 1 < nch) {
            int gk = kn + ac;
            if (arow_ok && gk < K) av2 = *(const float4*)(Abase + kn);
            int bk = kn + bkrow;
            bh2 = *(const float4*)(WH + bk * 128 + bcol);
            bl2 = *(const float4*)(WL + bk * 128 + bcol);
        }

        uint32_t ahi[2][4], alo[2][4];
#pragma unroll
        for (int mt = 0; mt < 2; mt++) {
            int rb = wm * 32 + mt * 16;
#pragma unroll
            for (int j = 0; j < 4; j++) {
                int row = rb + tq + (j & 1) * 8;
                int col = tr + (j >> 1) * 4;
                ahi[mt][j] = __float_as_uint(sAh[buf][row * 8 + col]);
                alo[mt][j] = __float_as_uint(sAl[buf][row * 8 + col]);
            }
        }

        uint32_t bhi[8][2], blo[8][2];
#pragma unroll
        for (int nt = 0; nt < 8; nt++) {
            int cb = wn * 64 + nt * 8 + tq;
            bhi[nt][0] = __float_as_uint(sBh[buf][tr * BSTRIDE + cb]);
            bhi[nt][1] = __float_as_uint(sBh[buf][(tr + 4) * BSTRIDE + cb]);
            blo[nt][0] = __float_as_uint(sBl[buf][tr * BSTRIDE + cb]);
            blo[nt][1] = __float_as_uint(sBl[buf][(tr + 4) * BSTRIDE + cb]);
        }

#pragma unroll
        for (int nt = 0; nt < 8; nt++)
#pragma unroll
            for (int mt = 0; mt < 2; mt++)
                mma_tf32(acc[mt][nt], ahi[mt], bhi[nt]);
#pragma unroll
        for (int nt = 0; nt < 8; nt++)
#pragma unroll
            for (int mt = 0; mt < 2; mt++)
                mma_tf32(acc[mt][nt], ahi[mt], blo[nt]);
#pragma unroll
        for (int nt = 0; nt < 8; nt++)
#pragma unroll
            for (int mt = 0; mt < 2; mt++)
                mma_tf32(acc[mt][nt], alo[mt], bhi[nt]);

        if (ch + 1 < nch) {
            int nb = buf ^ 1;
            float4 ah, al;
            ah.x = __uint_as_float(f2tf32(av2.x)); al.x = __uint_as_float(f2tf32(av2.x - ah.x));
            ah.y = __uint_as_float(f2tf32(av2.y)); al.y = __uint_as_float(f2tf32(av2.y - ah.y));
            ah.z = __uint_as_float(f2tf32(av2.z)); al.z = __uint_as_float(f2tf32(av2.z - ah.z));
            ah.w = __uint_as_float(f2tf32(av2.w)); al.w = __uint_as_float(f2tf32(av2.w - ah.w));
            *(float4*)&sAh[nb][ar * 8 + ac] = ah;
            *(float4*)&sAl[nb][ar * 8 + ac] = al;
            *(float4*)&sBh[nb][bkrow * BSTRIDE + bcol] = bh2;
            *(float4*)&sBl[nb][bkrow * BSTRIDE + bcol] = bl2;
            __syncthreads();
            buf = nb;
        }
    }

    float* C = wn ? g_xw_b : g_xw_a;
#pragma unroll
    for (int mt = 0; mt < 2; mt++) {
        int row0 = bm + wm * 32 + mt * 16 + tq;
#pragma unroll
        for (int nt = 0; nt < 8; nt++) {
            int col = nt * 8 + tr * 2;
            if (row0 < M)
                *(float2*)(C + (size_t)row0 * 64 + col) = make_float2(acc[mt][nt][0], acc[mt][nt][1]);
            if (row0 + 8 < M)
                *(float2*)(C + (size_t)(row0 + 8) * 64 + col) = make_float2(acc[mt][nt][2], acc[mt][nt][3]);
        }
    }
}

// ---------------- gather aggregation + combine + relu -> h ----------------
__global__ __launch_bounds__(64)
void k_gather64(const float* __restrict__ b_st, const float* __restrict__ b_ts) {
    int n = blockIdx.x;
    int c = threadIdx.x;
    int rs = g_rowstart[n], re = g_rowstart[n + 1];
    float acc_a = 0.f, acc_b = 0.f;
    int i = rs;
    for (; i + 3 < re; i += 4) {
        int   s0 = g_src_sorted[i],   s1 = g_src_sorted[i+1];
        int   s2 = g_src_sorted[i+2], s3 = g_src_sorted[i+3];
        float c0 = g_cdir_sorted[i],   c1 = g_cdir_sorted[i+1];
        float c2 = g_cdir_sorted[i+2], c3 = g_cdir_sorted[i+3];
        float v0 = (c0 >= 0.f) ? g_xw_a[s0 * 64 + c] : g_xw_b[s0 * 64 + c];
        float v1 = (c1 >= 0.f) ? g_xw_a[s1 * 64 + c] : g_xw_b[s1 * 64 + c];
        float v2 = (c2 >= 0.f) ? g_xw_a[s2 * 64 + c] : g_xw_b[s2 * 64 + c];
        float v3 = (c3 >= 0.f) ? g_xw_a[s3 * 64 + c] : g_xw_b[s3 * 64 + c];
        if (c0 >= 0.f) acc_a = fmaf(c0, v0, acc_a); else acc_b = fmaf(-c0, v0, acc_b);
        if (c1 >= 0.f) acc_a = fmaf(c1, v1, acc_a); else acc_b = fmaf(-c1, v1, acc_b);
        if (c2 >= 0.f) acc_a = fmaf(c2, v2, acc_a); else acc_b = fmaf(-c2, v2, acc_b);
        if (c3 >= 0.f) acc_a = fmaf(c3, v3, acc_a); else acc_b = fmaf(-c3, v3, acc_b);
    }
    for (; i < re; i++) {
        int   s0 = g_src_sorted[i];
        float c0 = g_cdir_sorted[i];
        float v0 = (c0 >= 0.f) ? g_xw_a[s0 * 64 + c] : g_xw_b[s0 * 64 + c];
        if (c0 >= 0.f) acc_a = fmaf(c0, v0, acc_a); else acc_b = fmaf(-c0, v0, acc_b);
    }
    float da = g_dinv_st[n], db = g_dinv_ts[n];
    float va = acc_a + g_xw_a[n * 64 + c] * da * da + b_st[c];
    float vb = acc_b + g_xw_b[n * 64 + c] * db * db + b_ts[c];
    g_h[n * 128 + c]      = fmaxf(va, 0.f);
    g_h[n * 128 + 64 + c] = fmaxf(vb, 0.f);
}

// ---------------- last layer: xw_l = h @ W_last ----------------
__global__ void k_gemm16(const float* __restrict__ Wl) {
    __shared__ float Ws[128 * 16];
    for (int i = threadIdx.x; i < 128 * 16; i += blockDim.x) Ws[i] = Wl[i];
    __syncthreads();
    int idx = blockIdx.x * blockDim.x + threadIdx.x;
    int n = idx >> 4;
    int j = idx & 15;
    if (n >= NN) return;
    const float* hr = g_h + (size_t)n * 128;
    float acc = 0.f;
#pragma unroll
    for (int k = 0; k < 128; k++) acc = fmaf(hr[k], Ws[k * 16 + j], acc);
    g_xw_l[n * 16 + j] = acc;
}

// ---------------- final gather + combine + log_softmax -> out ----------------
__global__ __launch_bounds__(128)
void k_gather16_final(const float* __restrict__ b_last, float* __restrict__ out) {
    int lid = threadIdx.x & 15;
    int grp = threadIdx.x >> 4;
    int n = blockIdx.x * 8 + grp;
    int rs = g_rowstart[n], re = g_rowstart[n + 1];
    float acc = 0.f;
    int i = rs;
    for (; i + 1 < re; i += 2) {
        int   s0 = g_src_sorted[i],  s1 = g_src_sorted[i+1];
        float f0 = g_call_sorted[i], f1 = g_call_sorted[i+1];
        acc = fmaf(f0, g_xw_l[s0 * 16 + lid], acc);
        acc = fmaf(f1, g_xw_l[s1 * 16 + lid], acc);
    }
    if (i < re) acc = fmaf(g_call_sorted[i], g_xw_l[g_src_sorted[i] * 16 + lid], acc);
    float dinv = g_dinv_all[n];
    float v = acc + g_xw_l[n * 16 + lid] * dinv * dinv + b_last[lid];
    float m = v;
#pragma unroll
    for (int o = 8; o > 0; o >>= 1) m = fmaxf(m, __shfl_xor_sync(0xFFFFFFFF, m, o, 16));
    float ex = expf(v - m);
    float ssum = ex;
#pragma unroll
    for (int o = 8; o > 0; o >>= 1) ssum += __shfl_xor_sync(0xFFFFFFFF, ssum, o, 16);
    out[n * 16 + lid] = v - (logf(ssum) + m);
}

// ---------------- launch ----------------
extern "C" void kernel_launch(void* const* d_in, const int* in_sizes, int n_in,
                              void* d_out, int out_size) {
    const float* x      = (const float*)d_in[0];
    const int*   ei     = (const int*)d_in[1];
    const void*  mrev   = d_in[2];
    const float* W_st0  = (const float*)d_in[3];
    const float* b_st0  = (const float*)d_in[4];
    const float* W_ts0  = (const float*)d_in[5];
    const float* b_ts0  = (const float*)d_in[6];
    const float* W_st1  = (const float*)d_in[7];
    const float* b_st1  = (const float*)d_in[8];
    const float* W_ts1  = (const float*)d_in[9];
    const float* b_ts1  = (const float*)d_in[10];
    const float* W_last = (const float*)d_in[11];
    const float* b_last = (const float*)d_in[12];
    float* out = (float*)d_out;

    const int* srcp = ei;
    const int* dstp = ei + EE;
    const int TB = 256;
    const int GEMM_BLOCKS = (NN + 127) / 128;

    // Aux stream + events (created once, on the first — non-captured — call;
    // host-side objects only, no device memory). Fork-join event pattern is
    // capture-legal and produces an identical graph every capture.
    static cudaStream_t s_aux = nullptr;
    static cudaEvent_t ev_fork = nullptr, ev_join = nullptr;
    if (s_aux == nullptr) {
        cudaStreamCreateWithFlags(&s_aux, cudaStreamNonBlocking);
        cudaEventCreateWithFlags(&ev_fork, cudaEventDisableTiming);
        cudaEventCreateWithFlags(&ev_join, cudaEventDisableTiming);
    }

    // fork aux off the main stream
    cudaEventRecord(ev_fork, 0);
    cudaStreamWaitEvent(s_aux, ev_fork, 0);

    // interleaved submission; aux chain: wsplit -> gemm L0 (launch idx 3 = profiled)
    k_prep<<<(200000 + TB - 1) / TB, TB>>>((const unsigned int*)mrev);        // 0 main
    k_wsplit<<<(K0PAD * 128 + TB - 1) / TB, TB, 0, s_aux>>>(W_st0, W_ts0, W_st1, W_ts1); // 1 aux
    k_hist<<<(EE + TB - 1) / TB, TB>>>(dstp, mrev);                           // 2 main
    k_gemm_tc<<<GEMM_BLOCKS, 256, 0, s_aux>>>(x, NN, FIN, 0, 0);              // 3 aux
    k_dinv<<<(NN + TB - 1) / TB, TB>>>();                                     // 4 main
    k_scan1<<<SCAN_B, 1024>>>();                                              // 5 main
    k_scan2<<<1, 64>>>();                                                     // 6 main
    k_scan3<<<SCAN_B, 1024>>>();                                              // 7 main
    k_fill<<<(EE + TB - 1) / TB, TB>>>(srcp, dstp, mrev);                     // 8 main

    // join: gather needs both CSR (main) and xw (aux)
    cudaEventRecord(ev_join, s_aux);
    cudaStreamWaitEvent(0, ev_join, 0);

    k_gather64<<<NN, 64>>>(b_st0, b_ts0);

    // layer 1 (serial: depends on h)
    k_gemm_tc<<<GEMM_BLOCKS, 256>>>(nullptr, NN, 2 * HH, 1, 1);
    k_gather64<<<NN, 64>>>(b_st1, b_ts1);

    // last layer
    k_gemm16<<<(NN * 16) / TB, TB>>>(W_last);
    k_gather16_final<<<NN / 8, 128>>>(b_last, out);
}

// round 17
// speedup vs baseline: 1.2107x; 1.1324x over previous
#include <cuda_runtime.h>
#include <cstdint>

#define NN 50000
#define EE 800000
#define FIN 500
#define HH 64
#define CO 16
#define SCAN_B 49     // ceil(NN/1024)
#define BSTRIDE 136   // B smem row stride in floats
#define K0PAD 504     // FIN padded to multiple of 8

// ---------------- scratch (device globals; allocation-free) ----------------
__device__ float g_xw_a[NN * HH];
__device__ float g_xw_b[NN * HH];
__device__ float g_h[NN * 2 * HH];
__device__ float g_xw_l[NN * CO];
__device__ float g_w0hi[K0PAD * 128], g_w0lo[K0PAD * 128];  // [k][col], cols=[Wst|Wts]
__device__ float g_w1hi[128 * 128],  g_w1lo[128 * 128];
__device__ int   g_degi_st[NN], g_degi_ts[NN];
__device__ int   g_degtot[NN];
__device__ int   g_rowstart[NN + 1];
__device__ int   g_cursor[NN];
__device__ int   g_bsum[SCAN_B];
__device__ int   g_boff[SCAN_B];
__device__ int   g_src_sorted[EE];
__device__ float g_cdir_sorted[EE];   // sign encodes branch: + => st (xw_a), - => ts (xw_b)
__device__ float g_call_sorted[EE];
__device__ float g_dinv_st[NN], g_dinv_ts[NN], g_dinv_all[NN];
__device__ int   g_flags[2];          // [0]=saw_float_bits, [1]=saw_byte_layout

// ---------------- helpers ----------------
__device__ __forceinline__ int edge_reversed(const void* m, int e) {
    if (g_flags[1]) return ((const unsigned char*)m)[e] != 0;
    if (g_flags[0]) return ((const float*)m)[e] != 0.0f;
    return ((const int*)m)[e] != 0;
}

__device__ __forceinline__ uint32_t f2tf32(float f) {
    uint32_t r;
    asm("cvt.rna.tf32.f32 %0, %1;" : "=r"(r) : "f"(f));
    return r;
}

__device__ __forceinline__ void mma_tf32(float* c, const uint32_t* a, const uint32_t* b) {
    asm volatile("mma.sync.aligned.m16n8k8.row.col.f32.tf32.tf32.f32 "
                 "{%0,%1,%2,%3}, {%4,%5,%6,%7}, {%8,%9}, {%0,%1,%2,%3};"
                 : "+f"(c[0]), "+f"(c[1]), "+f"(c[2]), "+f"(c[3])
                 : "r"(a[0]), "r"(a[1]), "r"(a[2]), "r"(a[3]), "r"(b[0]), "r"(b[1]));
}

// ---------------- prep: zero degree arrays + probe is_reversed layout ----------------
__global__ void k_prep(const unsigned int* __restrict__ m) {
    int i = blockIdx.x * blockDim.x + threadIdx.x;
    if (i < NN) { g_degi_st[i] = 0; g_degi_ts[i] = 0; }
    if (i < 2) g_flags[i] = 0;
    unsigned int sawF = 0, sawB = 0;
    if (i < 200000) {
        unsigned int w = m[i];
        if (w > 1u) { if (w == 0x3F800000u) sawF = 1; else sawB = 1; }
    }
    sawF = __any_sync(0xFFFFFFFF, sawF);
    sawB = __any_sync(0xFFFFFFFF, sawB);
    if ((threadIdx.x & 31) == 0) {
        if (sawF) atomicOr(&g_flags[0], 1);
        if (sawB) atomicOr(&g_flags[1], 1);
    }
}

// ---------------- degree histogram ----------------
__global__ void k_hist(const int* __restrict__ dst, const void* __restrict__ mrev) {
    int e = blockIdx.x * blockDim.x + threadIdx.x;
    if (e >= EE) return;
    int d = dst[e];
    if (edge_reversed(mrev, e)) atomicAdd(&g_degi_ts[d], 1);
    else                        atomicAdd(&g_degi_st[d], 1);
}

// ---------------- pre-split weights into tf32 hi/lo planes ----------------
__global__ void k_wsplit(const float* __restrict__ W_st0, const float* __restrict__ W_ts0,
                         const float* __restrict__ W_st1, const float* __restrict__ W_ts1) {
    int i = blockIdx.x * blockDim.x + threadIdx.x;
    if (i < K0PAD * 128) {
        int k = i >> 7, c = i & 127;
        float f = 0.f;
        if (k < FIN) f = (c < 64) ? W_st0[k * 64 + c] : W_ts0[k * 64 + (c - 64)];
        uint32_t hi = f2tf32(f);
        float fh = __uint_as_float(hi);
        g_w0hi[i] = fh;
        g_w0lo[i] = __uint_as_float(f2tf32(f - fh));
    }
    if (i < 128 * 128) {
        int k = i >> 7, c = i & 127;
        float f = (c < 64) ? W_st1[k * 64 + c] : W_ts1[k * 64 + (c - 64)];
        uint32_t hi = f2tf32(f);
        float fh = __uint_as_float(hi);
        g_w1hi[i] = fh;
        g_w1lo[i] = __uint_as_float(f2tf32(f - fh));
    }
}

__global__ void k_dinv() {
    int n = blockIdx.x * blockDim.x + threadIdx.x;
    if (n >= NN) return;
    int ids = g_degi_st[n], idt = g_degi_ts[n];
    float ds = (float)ids, dt = (float)idt;
    g_degtot[n] = ids + idt;
    g_dinv_st[n]  = rsqrtf(ds + 1.f);
    g_dinv_ts[n]  = rsqrtf(dt + 1.f);
    g_dinv_all[n] = rsqrtf(ds + dt + 1.f);
}

// ---------------- two-level exclusive scan of degtot -> rowstart ----------------
__global__ __launch_bounds__(1024)
void k_scan1() {
    int b = blockIdx.x, t = threadIdx.x;
    int i = b * 1024 + t;
    int v = (i < NN) ? g_degtot[i] : 0;
    int lane = t & 31, wid = t >> 5;
    int x = v;
#pragma unroll
    for (int o = 1; o < 32; o <<= 1) {
        int u = __shfl_up_sync(0xFFFFFFFF, x, o);
        if (lane >= o) x += u;
    }
    __shared__ int ws[32];
    if (lane == 31) ws[wid] = x;
    __syncthreads();
    if (wid == 0) {
        int s = ws[lane];
#pragma unroll
        for (int o = 1; o < 32; o <<= 1) {
            int u = __shfl_up_sync(0xFFFFFFFF, s, o);
            if (lane >= o) s += u;
        }
        ws[lane] = s;
    }
    __syncthreads();
    int incl = x + (wid > 0 ? ws[wid - 1] : 0);
    if (i < NN) g_rowstart[i] = incl - v;
    if (t == 1023) g_bsum[b] = incl;
}

__global__ __launch_bounds__(64)
void k_scan2() {
    int t = threadIdx.x;
    int v = (t < SCAN_B) ? g_bsum[t] : 0;
    int lane = t & 31, wid = t >> 5;
    int x = v;
#pragma unroll
    for (int o = 1; o < 32; o <<= 1) {
        int u = __shfl_up_sync(0xFFFFFFFF, x, o);
        if (lane >= o) x += u;
    }
    __shared__ int w0;
    if (wid == 0 && lane == 31) w0 = x;
    __syncthreads();
    int incl = x + (wid == 1 ? w0 : 0);
    if (t < SCAN_B) g_boff[t] = incl - v;
}

__global__ __launch_bounds__(1024)
void k_scan3() {
    int b = blockIdx.x, t = threadIdx.x;
    int i = b * 1024 + t;
    if (i < NN) {
        int r = g_rowstart[i] + g_boff[b];
        g_rowstart[i] = r;
        g_cursor[i] = r;
    }
    if (i == 0) g_rowstart[NN] = EE;
}

// ---------------- fill CSR buckets ----------------
__global__ void k_fill(const int* __restrict__ src, const int* __restrict__ dst,
                       const void* __restrict__ mrev) {
    int e = blockIdx.x * blockDim.x + threadIdx.x;
    if (e >= EE) return;
    int s = src[e], d = dst[e];
    int rev = edge_reversed(mrev, e);
    int pos = atomicAdd(&g_cursor[d], 1);
    float c = rev ? (g_dinv_ts[s] * g_dinv_ts[d]) : (g_dinv_st[s] * g_dinv_st[d]);
    g_src_sorted[pos]  = s;
    g_cdir_sorted[pos] = rev ? -c : c;
    g_call_sorted[pos] = g_dinv_all[s] * g_dinv_all[d];
}

// ---------------- tensor-core GEMM: C[M,128] = A[M,K] @ [Wa | Wb] -------------
__global__ __launch_bounds__(256)
void k_gemm_tc(const float* __restrict__ Aparam, int M, int K, int lsel, int asel) {
    const float* A  = asel ? g_h : Aparam;
    const float* WH = lsel ? g_w1hi : g_w0hi;
    const float* WL = lsel ? g_w1lo : g_w0lo;
    __shared__ float sAh[2][128 * 8], sAl[2][128 * 8];
    __shared__ float sBh[2][8 * BSTRIDE], sBl[2][8 * BSTRIDE];
    int tid = threadIdx.x;
    int wid = tid >> 5, lane = tid & 31;
    int wm = wid >> 1, wn = wid & 1;
    int tq = lane >> 2, tr = lane & 3;
    int bm = blockIdx.x * 128;

    int ar = tid >> 1, ac = (tid & 1) * 4;
    int bkrow = tid >> 5;
    int bcol = lane * 4;

    int agrow = bm + ar;
    bool arow_ok = agrow < M;
    const float* Abase = A + (size_t)agrow * K + ac;

    float acc[2][8][4];
#pragma unroll
    for (int mt = 0; mt < 2; mt++)
#pragma unroll
        for (int nt = 0; nt < 8; nt++)
#pragma unroll
            for (int j = 0; j < 4; j++) acc[mt][nt][j] = 0.f;

    int nch = (K + 7) / 8;

    {
        float4 av = make_float4(0.f, 0.f, 0.f, 0.f);
        if (arow_ok && ac < K) av = *(const float4*)(Abase);
        float4 ah, al;
        ah.x = __uint_as_float(f2tf32(av.x)); al.x = __uint_as_float(f2tf32(av.x - ah.x));
        ah.y = __uint_as_float(f2tf32(av.y)); al.y = __uint_as_float(f2tf32(av.y - ah.y));
        ah.z = __uint_as_float(f2tf32(av.z)); al.z = __uint_as_float(f2tf32(av.z - ah.z));
        ah.w = __uint_as_float(f2tf32(av.w)); al.w = __uint_as_float(f2tf32(av.w - ah.w));
        *(float4*)&sAh[0][ar * 8 + ac] = ah;
        *(float4*)&sAl[0][ar * 8 + ac] = al;
        float4 bh = *(const float4*)(WH + bkrow * 128 + bcol);
        float4 bl = *(const float4*)(WL + bkrow * 128 + bcol);
        *(float4*)&sBh[0][bkrow * BSTRIDE + bcol] = bh;
        *(float4*)&sBl[0][bkrow * BSTRIDE + bcol] = bl;
    }
    __syncthreads();

    int buf = 0;
    for (int ch = 0; ch < nch; ch++) {
        int kn = (ch + 1) * 8;
        float4 av2 = make_float4(0.f, 0.f, 0.f, 0.f);
        float4 bh2 = make_float4(0.f, 0.f, 0.f, 0.f);
        float4 bl2 = make_float4(0.f, 0.f, 0.f, 0.f);
        if (ch + 1 < nch) {
            int gk = kn + ac;
            if (arow_ok && gk < K) av2 = *(const float4*)(Abase + kn);
            int bk = kn + bkrow;
            bh2 = *(const float4*)(WH + bk * 128 + bcol);
            bl2 = *(const float4*)(WL + bk * 128 + bcol);
        }

        uint32_t ahi[2][4], alo[2][4];
#pragma unroll
        for (int mt = 0; mt < 2; mt++) {
            int rb = wm * 32 + mt * 16;
#pragma unroll
            for (int j = 0; j < 4; j++) {
                int row = rb + tq + (j & 1) * 8;
                int col = tr + (j >> 1) * 4;
                ahi[mt][j] = __float_as_uint(sAh[buf][row * 8 + col]);
                alo[mt][j] = __float_as_uint(sAl[buf][row * 8 + col]);
            }
        }

        uint32_t bhi[8][2], blo[8][2];
#pragma unroll
        for (int nt = 0; nt < 8; nt++) {
            int cb = wn * 64 + nt * 8 + tq;
            bhi[nt][0] = __float_as_uint(sBh[buf][tr * BSTRIDE + cb]);
            bhi[nt][1] = __float_as_uint(sBh[buf][(tr + 4) * BSTRIDE + cb]);
            blo[nt][0] = __float_as_uint(sBl[buf][tr * BSTRIDE + cb]);
            blo[nt][1] = __float_as_uint(sBl[buf][(tr + 4) * BSTRIDE + cb]);
        }

#pragma unroll
        for (int nt = 0; nt < 8; nt++)
#pragma unroll
            for (int mt = 0; mt < 2; mt++)
                mma_tf32(acc[mt][nt], ahi[mt], bhi[nt]);
#pragma unroll
        for (int nt = 0; nt < 8; nt++)
#pragma unroll
            for (int mt = 0; mt < 2; mt++)
                mma_tf32(acc[mt][nt], ahi[mt], blo[nt]);
#pragma unroll
        for (int nt = 0; nt < 8; nt++)
#pragma unroll
            for (int mt = 0; mt < 2; mt++)
                mma_tf32(acc[mt][nt], alo[mt], bhi[nt]);

        if (ch + 1 < nch) {
            int nb = buf ^ 1;
            float4 ah, al;
            ah.x = __uint_as_float(f2tf32(av2.x)); al.x = __uint_as_float(f2tf32(av2.x - ah.x));
            ah.y = __uint_as_float(f2tf32(av2.y)); al.y = __uint_as_float(f2tf32(av2.y - ah.y));
            ah.z = __uint_as_float(f2tf32(av2.z)); al.z = __uint_as_float(f2tf32(av2.z - ah.z));
            ah.w = __uint_as_float(f2tf32(av2.w)); al.w = __uint_as_float(f2tf32(av2.w - ah.w));
            *(float4*)&sAh[nb][ar * 8 + ac] = ah;
            *(float4*)&sAl[nb][ar * 8 + ac] = al;
            *(float4*)&sBh[nb][bkrow * BSTRIDE + bcol] = bh2;
            *(float4*)&sBl[nb][bkrow * BSTRIDE + bcol] = bl2;
            __syncthreads();
            buf = nb;
        }
    }

    float* C = wn ? g_xw_b : g_xw_a;
#pragma unroll
    for (int mt = 0; mt < 2; mt++) {
        int row0 = bm + wm * 32 + mt * 16 + tq;
#pragma unroll
        for (int nt = 0; nt < 8; nt++) {
            int col = nt * 8 + tr * 2;
            if (row0 < M)
                *(float2*)(C + (size_t)row0 * 64 + col) = make_float2(acc[mt][nt][0], acc[mt][nt][1]);
            if (row0 + 8 < M)
                *(float2*)(C + (size_t)(row0 + 8) * 64 + col) = make_float2(acc[mt][nt][2], acc[mt][nt][3]);
        }
    }
}

// ---------------- gather aggregation + combine + relu -> h ----------------
// 32 lanes per node, float2 per lane (one LDG.64 per edge-row per warp).
// Block = 128 threads = 4 nodes. NN % 4 == 0.
__global__ __launch_bounds__(128)
void k_gather64(const float* __restrict__ b_st, const float* __restrict__ b_ts) {
    int n = blockIdx.x * 4 + (threadIdx.x >> 5);
    int lane = threadIdx.x & 31;
    const float2* xa = (const float2*)g_xw_a;
    const float2* xb = (const float2*)g_xw_b;
    int rs = g_rowstart[n], re = g_rowstart[n + 1];
    float2 aa = make_float2(0.f, 0.f), ab = make_float2(0.f, 0.f);
    int i = rs;
    for (; i + 3 < re; i += 4) {
        int   s0 = g_src_sorted[i],   s1 = g_src_sorted[i+1];
        int   s2 = g_src_sorted[i+2], s3 = g_src_sorted[i+3];
        float c0 = g_cdir_sorted[i],   c1 = g_cdir_sorted[i+1];
        float c2 = g_cdir_sorted[i+2], c3 = g_cdir_sorted[i+3];
        float2 v0 = ((c0 >= 0.f) ? xa : xb)[s0 * 32 + lane];
        float2 v1 = ((c1 >= 0.f) ? xa : xb)[s1 * 32 + lane];
        float2 v2 = ((c2 >= 0.f) ? xa : xb)[s2 * 32 + lane];
        float2 v3 = ((c3 >= 0.f) ? xa : xb)[s3 * 32 + lane];
        if (c0 >= 0.f) { aa.x = fmaf(c0, v0.x, aa.x); aa.y = fmaf(c0, v0.y, aa.y); }
        else           { ab.x = fmaf(-c0, v0.x, ab.x); ab.y = fmaf(-c0, v0.y, ab.y); }
        if (c1 >= 0.f) { aa.x = fmaf(c1, v1.x, aa.x); aa.y = fmaf(c1, v1.y, aa.y); }
        else           { ab.x = fmaf(-c1, v1.x, ab.x); ab.y = fmaf(-c1, v1.y, ab.y); }
        if (c2 >= 0.f) { aa.x = fmaf(c2, v2.x, aa.x); aa.y = fmaf(c2, v2.y, aa.y); }
        else           { ab.x = fmaf(-c2, v2.x, ab.x); ab.y = fmaf(-c2, v2.y, ab.y); }
        if (c3 >= 0.f) { aa.x = fmaf(c3, v3.x, aa.x); aa.y = fmaf(c3, v3.y, aa.y); }
        else           { ab.x = fmaf(-c3, v3.x, ab.x); ab.y = fmaf(-c3, v3.y, ab.y); }
    }
    for (; i < re; i++) {
        int   s0 = g_src_sorted[i];
        float c0 = g_cdir_sorted[i];
        float2 v0 = ((c0 >= 0.f) ? xa : xb)[s0 * 32 + lane];
        if (c0 >= 0.f) { aa.x = fmaf(c0, v0.x, aa.x); aa.y = fmaf(c0, v0.y, aa.y); }
        else           { ab.x = fmaf(-c0, v0.x, ab.x); ab.y = fmaf(-c0, v0.y, ab.y); }
    }
    float da = g_dinv_st[n], db = g_dinv_ts[n];
    float2 xs = xa[n * 32 + lane], xt = xb[n * 32 + lane];
    float2 bs = ((const float2*)b_st)[lane], bt = ((const float2*)b_ts)[lane];
    float d2a = da * da, d2b = db * db;
    float2 va, vb;
    va.x = fmaxf(aa.x + xs.x * d2a + bs.x, 0.f);
    va.y = fmaxf(aa.y + xs.y * d2a + bs.y, 0.f);
    vb.x = fmaxf(ab.x + xt.x * d2b + bt.x, 0.f);
    vb.y = fmaxf(ab.y + xt.y * d2b + bt.y, 0.f);
    ((float2*)g_h)[n * 64 + lane]      = va;
    ((float2*)g_h)[n * 64 + 32 + lane] = vb;
}

// ---------------- last layer: xw_l = h @ W_last ----------------
// Block = 256 threads = 16 nodes x 16 cols; h rows staged in smem (coalesced).
__global__ __launch_bounds__(256)
void k_gemm16(const float* __restrict__ Wl) {
    __shared__ float Ws[128 * 16];
    __shared__ float hs[16 * 128];
    int tid = threadIdx.x;
    for (int i = tid; i < 128 * 16; i += 256) Ws[i] = Wl[i];
    int nb = blockIdx.x * 16;           // NN % 16 == 0
    const float4* hsrc = (const float4*)(g_h + (size_t)nb * 128);
    float4* hd = (float4*)hs;
#pragma unroll
    for (int i = tid; i < 512; i += 256) hd[i] = hsrc[i];
    __syncthreads();
    int g = tid >> 4, j = tid & 15;
    const float* hr = hs + g * 128;
    float acc = 0.f;
#pragma unroll
    for (int k = 0; k < 128; k++) acc = fmaf(hr[k], Ws[k * 16 + j], acc);
    g_xw_l[(nb + g) * 16 + j] = acc;
}

// ---------------- final gather + combine + log_softmax -> out ----------------
__global__ __launch_bounds__(128)
void k_gather16_final(const float* __restrict__ b_last, float* __restrict__ out) {
    int lid = threadIdx.x & 15;
    int grp = threadIdx.x >> 4;
    int n = blockIdx.x * 8 + grp;
    int rs = g_rowstart[n], re = g_rowstart[n + 1];
    float acc = 0.f;
    int i = rs;
    for (; i + 1 < re; i += 2) {
        int   s0 = g_src_sorted[i],  s1 = g_src_sorted[i+1];
        float f0 = g_call_sorted[i], f1 = g_call_sorted[i+1];
        acc = fmaf(f0, g_xw_l[s0 * 16 + lid], acc);
        acc = fmaf(f1, g_xw_l[s1 * 16 + lid], acc);
    }
    if (i < re) acc = fmaf(g_call_sorted[i], g_xw_l[g_src_sorted[i] * 16 + lid], acc);
    float dinv = g_dinv_all[n];
    float v = acc + g_xw_l[n * 16 + lid] * dinv * dinv + b_last[lid];
    float m = v;
#pragma unroll
    for (int o = 8; o > 0; o >>= 1) m = fmaxf(m, __shfl_xor_sync(0xFFFFFFFF, m, o, 16));
    float ex = expf(v - m);
    float ssum = ex;
#pragma unroll
    for (int o = 8; o > 0; o >>= 1) ssum += __shfl_xor_sync(0xFFFFFFFF, ssum, o, 16);
    out[n * 16 + lid] = v - (logf(ssum) + m);
}

// ---------------- launch ----------------
extern "C" void kernel_launch(void* const* d_in, const int* in_sizes, int n_in,
                              void* d_out, int out_size) {
    const float* x      = (const float*)d_in[0];
    const int*   ei     = (const int*)d_in[1];
    const void*  mrev   = d_in[2];
    const float* W_st0  = (const float*)d_in[3];
    const float* b_st0  = (const float*)d_in[4];
    const float* W_ts0  = (const float*)d_in[5];
    const float* b_ts0  = (const float*)d_in[6];
    const float* W_st1  = (const float*)d_in[7];
    const float* b_st1  = (const float*)d_in[8];
    const float* W_ts1  = (const float*)d_in[9];
    const float* b_ts1  = (const float*)d_in[10];
    const float* W_last = (const float*)d_in[11];
    const float* b_last = (const float*)d_in[12];
    float* out = (float*)d_out;

    const int* srcp = ei;
    const int* dstp = ei + EE;
    const int TB = 256;
    const int GEMM_BLOCKS = (NN + 127) / 128;

    static cudaStream_t s_aux = nullptr;
    static cudaEvent_t ev_fork = nullptr, ev_join = nullptr;
    if (s_aux == nullptr) {
        cudaStreamCreateWithFlags(&s_aux, cudaStreamNonBlocking);
        cudaEventCreateWithFlags(&ev_fork, cudaEventDisableTiming);
        cudaEventCreateWithFlags(&ev_join, cudaEventDisableTiming);
    }

    cudaEventRecord(ev_fork, 0);
    cudaStreamWaitEvent(s_aux, ev_fork, 0);

    k_prep<<<(200000 + TB - 1) / TB, TB>>>((const unsigned int*)mrev);        // 0 main
    k_wsplit<<<(K0PAD * 128 + TB - 1) / TB, TB, 0, s_aux>>>(W_st0, W_ts0, W_st1, W_ts1); // 1 aux
    k_hist<<<(EE + TB - 1) / TB, TB>>>(dstp, mrev);                           // 2 main
    k_gemm_tc<<<GEMM_BLOCKS, 256, 0, s_aux>>>(x, NN, FIN, 0, 0);              // 3 aux (profiled)
    k_dinv<<<(NN + TB - 1) / TB, TB>>>();                                     // 4 main
    k_scan1<<<SCAN_B, 1024>>>();                                              // 5 main
    k_scan2<<<1, 64>>>();                                                     // 6 main
    k_scan3<<<SCAN_B, 1024>>>();                                              // 7 main
    k_fill<<<(EE + TB - 1) / TB, TB>>>(srcp, dstp, mrev);                     // 8 main

    cudaEventRecord(ev_join, s_aux);
    cudaStreamWaitEvent(0, ev_join, 0);

    k_gather64<<<NN / 4, 128>>>(b_st0, b_ts0);

    k_gemm_tc<<<GEMM_BLOCKS, 256>>>(nullptr, NN, 2 * HH, 1, 1);
    k_gather64<<<NN / 4, 128>>>(b_st1, b_ts1);

    k_gemm16<<<NN / 16, 256>>>(W_last);
    k_gather16_final<<<NN / 8, 128>>>(b_last, out);
}